// round 1
// baseline (speedup 1.0000x reference)
#include <cuda_runtime.h>
#include <cstdint>

// ---------------------------------------------------------------------------
// Problem: v = W[256,512] @ x_vit[b][512,32*32] + bias        (per batch, 8x)
//          v_up = bilinear 4x upsample (half-pixel centers)   (32x32 -> 128x128)
//          out[b,0,y,x] = cos_sim over 256 channels of (x_cnn[b,:,y,x], v_up[b,:,y,x])
// ---------------------------------------------------------------------------

#define BATCH 8
#define CH    256     // output channels (M)
#define KDIM  512     // vit channels (K)
#define VHW   1024    // 32*32 (N per batch)
#define H_OUT 128
#define W_OUT 128

// scratch for v: 8 * 256 * 1024 floats = 8 MiB (fits easily in L2 for kernel B)
__device__ float g_v[BATCH * CH * VHW];

// packed f32x2 FMA (sm_100+ / sm_103a). One instruction = 2 fp32 FMAs per lane.
__device__ __forceinline__ unsigned long long ffma2(unsigned long long a,
                                                    unsigned long long b,
                                                    unsigned long long c) {
    unsigned long long d;
    asm("fma.rn.f32x2 %0, %1, %2, %3;" : "=l"(d) : "l"(a), "l"(b), "l"(c));
    return d;
}

// ---------------------------------------------------------------------------
// Kernel A: per-batch GEMM  C[256,1024] = W[256,512] @ X[512,1024] + bias
// BM=64, BN=128, BK=32, 128 threads, each thread computes 8x8 outputs
// via f32x2 packed FMAs (column pairs).
// ---------------------------------------------------------------------------
#define GA_BM 64
#define GA_BN 128
#define GA_BK 32

__global__ __launch_bounds__(128)
void gemm_bias_kernel(const float* __restrict__ Wmat,
                      const float* __restrict__ xvit,
                      const float* __restrict__ bias) {
    const int bx = blockIdx.x;           // N tile
    const int by = blockIdx.y;           // M tile
    const int bb = blockIdx.z;           // batch
    const int n0 = bx * GA_BN;
    const int m0 = by * GA_BM;

    const float* B = xvit + (size_t)bb * KDIM * VHW;
    float*       C = g_v  + (size_t)bb * CH * VHW;

    // A stored splatted ({w,w}) so FFMA2 "a" operand needs no shuffle.
    __shared__ float2 As[GA_BK][GA_BM + 1];   // +1 pad kills STS bank conflicts
    __shared__ float  Bs[GA_BK][GA_BN];

    const int tid = threadIdx.x;
    const int tn  = tid & 15;    // col group: columns tn*8 .. tn*8+7
    const int tmg = tid >> 4;    // row group: rows tmg*8 .. tmg*8+7

    unsigned long long acc[8][4];
    #pragma unroll
    for (int i = 0; i < 8; i++)
        #pragma unroll
        for (int j = 0; j < 4; j++) acc[i][j] = 0ull;

    for (int kt = 0; kt < KDIM; kt += GA_BK) {
        __syncthreads();
        // fill A tile: 64 rows x 32 k  (coalesced reads of W)
        #pragma unroll
        for (int i = tid; i < GA_BM * GA_BK; i += 128) {
            int r = i >> 5;        // m row within tile
            int c = i & 31;        // k col within tile
            float w = Wmat[(size_t)(m0 + r) * KDIM + kt + c];
            As[c][r] = make_float2(w, w);
        }
        // fill B tile: 32 k-rows x 128 cols (float4 coalesced)
        #pragma unroll
        for (int i = tid; i < (GA_BK * GA_BN) / 4; i += 128) {
            int r  = i >> 5;       // k row
            int c4 = i & 31;       // float4 col
            float4 v = *(const float4*)&B[(size_t)(kt + r) * VHW + n0 + c4 * 4];
            *(float4*)&Bs[r][c4 * 4] = v;
        }
        __syncthreads();

        #pragma unroll
        for (int kk = 0; kk < GA_BK; kk++) {
            unsigned long long a2[8], b2[4];
            #pragma unroll
            for (int i = 0; i < 8; i++)
                a2[i] = *(const unsigned long long*)&As[kk][tmg * 8 + i];
            const float* brow = &Bs[kk][tn * 8];
            #pragma unroll
            for (int j = 0; j < 4; j++)
                b2[j] = *(const unsigned long long*)&brow[2 * j];
            #pragma unroll
            for (int i = 0; i < 8; i++)
                #pragma unroll
                for (int j = 0; j < 4; j++)
                    acc[i][j] = ffma2(a2[i], b2[j], acc[i][j]);
        }
    }

    // epilogue: add bias, store
    #pragma unroll
    for (int i = 0; i < 8; i++) {
        int m = m0 + tmg * 8 + i;
        float bv = bias[m];
        float o[8];
        #pragma unroll
        for (int j = 0; j < 4; j++) {
            o[2 * j]     = __uint_as_float((unsigned)(acc[i][j] & 0xffffffffull)) + bv;
            o[2 * j + 1] = __uint_as_float((unsigned)(acc[i][j] >> 32)) + bv;
        }
        float* dst = &C[(size_t)m * VHW + n0 + tn * 8];
        *(float4*)(dst)     = make_float4(o[0], o[1], o[2], o[3]);
        *(float4*)(dst + 4) = make_float4(o[4], o[5], o[6], o[7]);
    }
}

// ---------------------------------------------------------------------------
// Kernel B: fused bilinear-upsample + per-pixel cosine similarity.
// Each 256-thread block covers a 64(w) x 4(h) output tile of one batch.
// Coarse v footprint for that tile: 3 rows x 18 cols per channel; staged in
// smem for 128 channels at a time (27.6 KB static).
// src coordinate: s = x*0.25 - 0.375 (half-pixel, scale 4); 2-tap, edge clamp
// (identical to jax's zero+renormalize at edges for the 2-tap case).
// ---------------------------------------------------------------------------
#define TB_W 64
#define TB_H 4
#define CCHUNK 128

__global__ __launch_bounds__(256)
void fused_cossim_kernel(const float* __restrict__ xcnn,
                         float* __restrict__ out) {
    const int bb = blockIdx.z;
    const int tx = threadIdx.x & (TB_W - 1);
    const int ty = threadIdx.x >> 6;
    const int x  = blockIdx.x * TB_W + tx;
    const int y  = blockIdx.y * TB_H + ty;

    __shared__ float vs[CCHUNK][54];    // [channel][yy*18+xx]

    const int cxb = (int)blockIdx.x * 16 - 1;   // coarse col base (may be -1)
    const int cyb = (int)blockIdx.y - 1;        // coarse row base (may be -1)

    // interpolation coords/weights (compile-exact fp32 quarters)
    float sx = x * 0.25f - 0.375f;
    float cx0f = floorf(sx);
    float fx = sx - cx0f;
    int   xx0 = (int)cx0f - cxb;        // 0..16
    float sy = y * 0.25f - 0.375f;
    float cy0f = floorf(sy);
    float fy = sy - cy0f;
    int   yy0 = (int)cy0f - cyb;        // 0..1
    const int soff = yy0 * 18 + xx0;

    const float w11 = fx * fy;
    const float w10 = fy - w11;
    const float w01 = fx - w11;
    const float w00 = 1.0f - fx - fy + w11;

    float dot = 0.f, scnn = 0.f, svit = 0.f;

    const float* xcb   = xcnn + ((size_t)bb * CH) * (H_OUT * W_OUT) + (size_t)y * W_OUT + x;
    const float* vbase = g_v  + (size_t)bb * CH * VHW;

    for (int c0 = 0; c0 < CH; c0 += CCHUNK) {
        __syncthreads();
        // stage coarse v tile for this channel chunk (clamped gather)
        for (int j = threadIdx.x; j < CCHUNK * 54; j += 256) {
            int c = j / 54;
            int r = j - c * 54;
            int yy = r / 18;
            int xx = r - yy * 18;
            int gy = min(max(cyb + yy, 0), 31);
            int gx = min(max(cxb + xx, 0), 31);
            vs[c][r] = vbase[(size_t)(c0 + c) * VHW + gy * 32 + gx];
        }
        __syncthreads();

        const float* xp = xcb + (size_t)c0 * (H_OUT * W_OUT);
        #pragma unroll 4
        for (int c = 0; c < CCHUNK; c++) {
            float xv = xp[(size_t)c * (H_OUT * W_OUT)];
            const float* vr = &vs[c][soff];
            float v00 = vr[0], v01 = vr[1], v10 = vr[18], v11 = vr[19];
            float vu = w00 * v00 + w01 * v01 + w10 * v10 + w11 * v11;
            dot  += xv * vu;
            scnn += xv * xv;
            svit += vu * vu;
        }
    }

    out[((size_t)bb * H_OUT + y) * W_OUT + x] =
        dot / (sqrtf(scnn) * sqrtf(svit) + 1e-8f);
}

// ---------------------------------------------------------------------------
extern "C" void kernel_launch(void* const* d_in, const int* in_sizes, int n_in,
                              void* d_out, int out_size) {
    const float* x_cnn = (const float*)d_in[0];   // [8,256,128,128]
    const float* x_vit = (const float*)d_in[1];   // [8,512,32,32]
    const float* Wmat  = (const float*)d_in[2];   // [256,512]
    const float* bias  = (const float*)d_in[3];   // [256]
    float* out = (float*)d_out;                   // [8,1,128,128]

    dim3 gA(VHW / GA_BN, CH / GA_BM, BATCH);      // (8, 4, 8)
    gemm_bias_kernel<<<gA, 128>>>(Wmat, x_vit, bias);

    dim3 gB(W_OUT / TB_W, H_OUT / TB_H, BATCH);   // (2, 32, 8)
    fused_cossim_kernel<<<gB, 256>>>(x_cnn, out);
}

// round 2
// speedup vs baseline: 1.1352x; 1.1352x over previous
#include <cuda_runtime.h>
#include <cstdint>

#define BATCH 8
#define CH    256
#define KDIM  512
#define VHW   1024     // 32*32
#define H_OUT 128
#define W_OUT 128

// scratch for v: 8 MiB, stays L2-resident between kernels
__device__ float g_v[BATCH * CH * VHW];

typedef unsigned long long ull;

__device__ __forceinline__ ull ffma2(ull a, ull b, ull c) {
    ull d;
    asm("fma.rn.f32x2 %0, %1, %2, %3;" : "=l"(d) : "l"(a), "l"(b), "l"(c));
    return d;
}
__device__ __forceinline__ ull splat2(float x) {
    ull r; asm("mov.b64 %0, {%1, %1};" : "=l"(r) : "f"(x)); return r;
}
__device__ __forceinline__ float2 unpack2(ull v) {
    float2 f; asm("mov.b64 {%0, %1}, %2;" : "=f"(f.x), "=f"(f.y) : "l"(v)); return f;
}

// ---------------------------------------------------------------------------
// Kernel A: per-batch GEMM  C[256,1024] = W[256,512] @ X[512,1024] + bias
// BM=128, BN=64, BK=16, 256 threads, double-buffered smem, one sync/tile.
// Accumulators packed over m-pairs (f32x2); A in smem transposed [k][m] so
// a-frags are direct broadcast LDS.64; only B values need splat MOVs.
// ---------------------------------------------------------------------------
#define A_BM 128
#define A_BN 64
#define A_BK 16
#define A_PAD 130      // m-stride: even (8B-aligned float2) + conflict-free STS

__global__ __launch_bounds__(256)
void gemm_bias_kernel(const float* __restrict__ Wmat,
                      const float* __restrict__ xvit,
                      const float* __restrict__ bias) {
    const int n0 = blockIdx.x * A_BN;
    const int m0 = blockIdx.y * A_BM;
    const float* Bg = xvit + (size_t)blockIdx.z * KDIM * VHW;
    float* Cg = g_v + (size_t)blockIdx.z * CH * VHW;

    __shared__ float As[2][A_BK * A_PAD];   // [k][m], 2 x 8.1 KB
    __shared__ float Bs[2][A_BK * A_BN];    // [k][n], 2 x 4 KB

    const int tid = threadIdx.x;
    const int ak  = tid & 15;          // k within tile (A load)
    const int amr = tid >> 4;          // m rows amr + 16q
    const int bk  = tid >> 4;          // k row (B load)
    const int bn  = (tid & 15) * 4;    // n float4 (B load)
    const int mg  = (tid >> 4) * 8;    // compute: m base (8 rows = 4 pairs)
    const int ng  = (tid & 15) * 4;    // compute: n base (4 cols)

    const float* wp = Wmat + (size_t)(m0 + amr) * KDIM + ak;
    const float* bp = Bg + (size_t)bk * VHW + n0 + bn;

    float  wa[8];
    float4 wb;

    // tile 0: LDG + STS
    #pragma unroll
    for (int q = 0; q < 8; q++) wa[q] = wp[(size_t)(16 * q) * KDIM];
    wb = *(const float4*)bp;
    #pragma unroll
    for (int q = 0; q < 8; q++) As[0][ak * A_PAD + amr + 16 * q] = wa[q];
    *(float4*)&Bs[0][bk * A_BN + bn] = wb;
    __syncthreads();
    // prefetch tile 1 into regs
    #pragma unroll
    for (int q = 0; q < 8; q++) wa[q] = wp[16 + (size_t)(16 * q) * KDIM];
    wb = *(const float4*)&bp[(size_t)16 * VHW];

    ull acc[4][4];
    #pragma unroll
    for (int i = 0; i < 4; i++)
        #pragma unroll
        for (int j = 0; j < 4; j++) acc[i][j] = 0ull;

    const int NT = KDIM / A_BK;   // 32 tiles
    int buf = 0;
    for (int t = 0; t < NT; t++) {
        #pragma unroll
        for (int kk = 0; kk < A_BK; kk++) {
            ull a2[4], b2[4];
            #pragma unroll
            for (int i = 0; i < 4; i++)
                a2[i] = *(const ull*)&As[buf][kk * A_PAD + mg + 2 * i];
            float4 bv = *(const float4*)&Bs[buf][kk * A_BN + ng];
            b2[0] = splat2(bv.x); b2[1] = splat2(bv.y);
            b2[2] = splat2(bv.z); b2[3] = splat2(bv.w);
            #pragma unroll
            for (int i = 0; i < 4; i++)
                #pragma unroll
                for (int j = 0; j < 4; j++)
                    acc[i][j] = ffma2(a2[i], b2[j], acc[i][j]);
        }
        if (t < NT - 1) {
            // store prefetched tile into the other buffer (safe: its readers
            // finished before the previous iteration's barrier)
            #pragma unroll
            for (int q = 0; q < 8; q++)
                As[buf ^ 1][ak * A_PAD + amr + 16 * q] = wa[q];
            *(float4*)&Bs[buf ^ 1][bk * A_BN + bn] = wb;
            __syncthreads();
            buf ^= 1;
            if (t < NT - 2) {
                const int kt = (t + 2) * A_BK;
                #pragma unroll
                for (int q = 0; q < 8; q++)
                    wa[q] = wp[kt + (size_t)(16 * q) * KDIM];
                wb = *(const float4*)&bp[(size_t)kt * VHW];
            }
        }
    }

    // epilogue: unpack m-pairs, add bias, float4 stores
    #pragma unroll
    for (int i = 0; i < 4; i++) {
        const int me = m0 + mg + 2 * i;
        const float be = bias[me];
        const float bo = bias[me + 1];
        float2 p0 = unpack2(acc[i][0]), p1 = unpack2(acc[i][1]);
        float2 p2 = unpack2(acc[i][2]), p3 = unpack2(acc[i][3]);
        float4 ve = make_float4(p0.x + be, p1.x + be, p2.x + be, p3.x + be);
        float4 vo = make_float4(p0.y + bo, p1.y + bo, p2.y + bo, p3.y + bo);
        *(float4*)&Cg[(size_t)me * VHW + n0 + ng] = ve;
        *(float4*)&Cg[(size_t)(me + 1) * VHW + n0 + ng] = vo;
    }
}

// ---------------------------------------------------------------------------
// Kernel B: fused bilinear-upsample + per-pixel cosine similarity.
// 128 threads/block, tile 128(w) x 4(h), 4 pixels/thread via LDG.128.
// Coarse v window (3 rows x 34 cols per channel) staged in smem with
// precomputed (no-division) offsets. Factored lerp: shared vertical lerp
// per window column + shared horizontal deltas -> 6 LDS + ~24 FMA / channel.
// ---------------------------------------------------------------------------
#define CB_CCH   64
#define CB_ELEMS 102   // 3 rows * 34 cols

__global__ __launch_bounds__(128)
void fused_cossim_kernel(const float* __restrict__ xcnn,
                         float* __restrict__ out) {
    const int bb   = blockIdx.z;
    const int by   = blockIdx.y;          // fine rows by*4 .. by*4+3
    const int lane = threadIdx.x & 31;    // x-group: pixels lane*4 .. lane*4+3
    const int wrp  = threadIdx.x >> 5;    // 0..3 = ty (and staging group)
    const int y    = by * 4 + wrp;
    const int x0   = lane * 4;

    __shared__ float vsf[CB_CCH * CB_ELEMS];   // 25.5 KB

    // precompute staging gather offsets (channel-invariant)
    int gsrc[4];
    #pragma unroll
    for (int e = 0; e < 4; e++) {
        int idx = lane + 32 * e;
        int yy = idx / 34;
        int xx = idx - yy * 34;
        int gy = min(max(by - 1 + yy, 0), 31);
        int gx = min(max(xx - 1, 0), 31);
        gsrc[e] = gy * 32 + gx;
    }
    const bool valid3 = (lane + 96) < CB_ELEMS;

    // y-phase: fine row y = 4*by + wrp; src = y/4 - 0.375
    const float fy = (wrp == 0) ? 0.625f : (wrp == 1) ? 0.875f
                   : (wrp == 2) ? 0.125f : 0.375f;
    const int rb = (wrp >= 2) ? 34 : 0;   // top window row offset

    float dot0=0.f,dot1=0.f,dot2=0.f,dot3=0.f;
    float sc0=0.f,sc1=0.f,sc2=0.f,sc3=0.f;
    float sv0=0.f,sv1=0.f,sv2=0.f,sv3=0.f;

    const float* xp = xcnn + (size_t)(bb * CH) * (H_OUT * W_OUT)
                    + (size_t)y * W_OUT + x0;
    const float* vbase = g_v + (size_t)bb * CH * VHW;

    for (int c0 = 0; c0 < CH; c0 += CB_CCH) {
        __syncthreads();
        // stage coarse window for this channel chunk (warp w -> channels w,w+4,..)
        for (int c = wrp; c < CB_CCH; c += 4) {
            const float* vc = vbase + (size_t)(c0 + c) * VHW;
            float t0 = vc[gsrc[0]];
            float t1 = vc[gsrc[1]];
            float t2 = vc[gsrc[2]];
            float* d = &vsf[c * CB_ELEMS + lane];
            d[0] = t0; d[32] = t1; d[64] = t2;
            if (valid3) d[96] = vc[gsrc[3]];
        }
        __syncthreads();

        const float* xc = xp + (size_t)c0 * (H_OUT * W_OUT);
        #pragma unroll 8
        for (int c = 0; c < CB_CCH; c++) {
            float4 x4 = *(const float4*)(xc + (size_t)c * (H_OUT * W_OUT));
            const float* v0 = &vsf[c * CB_ELEMS + rb + lane];
            float a0 = v0[0],  a1 = v0[1],  a2 = v0[2];
            float b0 = v0[34], b1 = v0[35], b2 = v0[36];
            // vertical lerp (shared per window column)
            float cv0 = fmaf(fy, b0 - a0, a0);
            float cv1 = fmaf(fy, b1 - a1, a1);
            float cv2 = fmaf(fy, b2 - a2, a2);
            // horizontal lerps, shared deltas
            float d01 = cv1 - cv0, d12 = cv2 - cv1;
            float vu0 = fmaf(0.625f, d01, cv0);
            float vu1 = fmaf(0.875f, d01, cv0);
            float vu2 = fmaf(0.125f, d12, cv1);
            float vu3 = fmaf(0.375f, d12, cv1);
            dot0 = fmaf(x4.x, vu0, dot0); sc0 = fmaf(x4.x, x4.x, sc0); sv0 = fmaf(vu0, vu0, sv0);
            dot1 = fmaf(x4.y, vu1, dot1); sc1 = fmaf(x4.y, x4.y, sc1); sv1 = fmaf(vu1, vu1, sv1);
            dot2 = fmaf(x4.z, vu2, dot2); sc2 = fmaf(x4.z, x4.z, sc2); sv2 = fmaf(vu2, vu2, sv2);
            dot3 = fmaf(x4.w, vu3, dot3); sc3 = fmaf(x4.w, x4.w, sc3); sv3 = fmaf(vu3, vu3, sv3);
        }
    }

    float4 o;
    o.x = dot0 / (sqrtf(sc0) * sqrtf(sv0) + 1e-8f);
    o.y = dot1 / (sqrtf(sc1) * sqrtf(sv1) + 1e-8f);
    o.z = dot2 / (sqrtf(sc2) * sqrtf(sv2) + 1e-8f);
    o.w = dot3 / (sqrtf(sc3) * sqrtf(sv3) + 1e-8f);
    *(float4*)&out[(size_t)bb * (H_OUT * W_OUT) + (size_t)y * W_OUT + x0] = o;
}

// ---------------------------------------------------------------------------
extern "C" void kernel_launch(void* const* d_in, const int* in_sizes, int n_in,
                              void* d_out, int out_size) {
    const float* x_cnn = (const float*)d_in[0];   // [8,256,128,128]
    const float* x_vit = (const float*)d_in[1];   // [8,512,32,32]
    const float* Wmat  = (const float*)d_in[2];   // [256,512]
    const float* bias  = (const float*)d_in[3];   // [256]
    float* out = (float*)d_out;                   // [8,1,128,128]

    dim3 gA(VHW / A_BN, CH / A_BM, BATCH);        // (16, 2, 8)
    gemm_bias_kernel<<<gA, 256>>>(Wmat, x_vit, bias);

    dim3 gB(1, H_OUT / 4, BATCH);                 // (1, 32, 8)
    fused_cossim_kernel<<<gB, 128>>>(x_cnn, out);
}

// round 3
// speedup vs baseline: 1.3849x; 1.2200x over previous
#include <cuda_runtime.h>
#include <cuda_bf16.h>
#include <cstdint>

#define BATCH 8
#define CH    256
#define KDIM  512
#define KP    256      // KDIM/2 packed bf16 pairs
#define VHW   1024     // 32*32
#define H_OUT 128
#define W_OUT 128
#define HWOUT (H_OUT * W_OUT)

// v scratch (8 MiB, L2-resident)
__device__ float g_v[BATCH * CH * VHW];
// bf16-split packed operands (pairs along k)
__device__ unsigned g_Wh[CH * KP];
__device__ unsigned g_Wl[CH * KP];
__device__ unsigned g_Xh[BATCH * KP * VHW];
__device__ unsigned g_Xl[BATCH * KP * VHW];
// cossim partials: [s(3)][chunk(4)][b(8)][pix(16384)]
__device__ float g_part[3 * 4 * BATCH * HWOUT];

// ---------------------------------------------------------------------------
// Converter: fp32 -> (bf16 hi, bf16 lo) packed k-pairs for W and x_vit.
// ---------------------------------------------------------------------------
__device__ __forceinline__ void split1(float x, unsigned short& h, unsigned short& l) {
    __nv_bfloat16 hb = __float2bfloat16(x);
    float r = x - __bfloat162float(hb);
    __nv_bfloat16 lb = __float2bfloat16(r);
    h = __bfloat16_as_ushort(hb);
    l = __bfloat16_as_ushort(lb);
}
__device__ __forceinline__ void pack2(float a, float b, unsigned& hi, unsigned& lo) {
    unsigned short h0, l0, h1, l1;
    split1(a, h0, l0);
    split1(b, h1, l1);
    hi = (unsigned)h0 | ((unsigned)h1 << 16);
    lo = (unsigned)l0 | ((unsigned)l1 << 16);
}

__global__ __launch_bounds__(256)
void convert_kernel(const float* __restrict__ xvit, const float* __restrict__ Wmat) {
    const int gid = blockIdx.x * 256 + threadIdx.x;   // 524288 total
    const int n4 = gid & 255;          // n = n4*4
    const int kp = (gid >> 8) & 255;
    const int b  = gid >> 16;

    {   // X: rows 2kp, 2kp+1, 4 columns
        const float* xs = xvit + ((size_t)(b * KDIM + 2 * kp) * VHW) + n4 * 4;
        float4 r0 = *(const float4*)xs;
        float4 r1 = *(const float4*)(xs + VHW);
        uint4 hi, lo;
        pack2(r0.x, r1.x, hi.x, lo.x);
        pack2(r0.y, r1.y, hi.y, lo.y);
        pack2(r0.z, r1.z, hi.z, lo.z);
        pack2(r0.w, r1.w, hi.w, lo.w);
        size_t o = ((size_t)(b * KP + kp) * VHW) + n4 * 4;
        *(uint4*)&g_Xh[o] = hi;
        *(uint4*)&g_Xl[o] = lo;
    }
    if (gid < CH * 64) {   // W: m = gid>>6, kp-quad = gid&63
        const int m = gid >> 6;
        const int kq = gid & 63;       // covers kp kq*4 .. kq*4+3 (k kq*8..+7)
        const float* ws = Wmat + (size_t)m * KDIM + kq * 8;
        float4 r0 = *(const float4*)ws;
        float4 r1 = *(const float4*)(ws + 4);
        uint4 hi, lo;
        pack2(r0.x, r0.y, hi.x, lo.x);
        pack2(r0.z, r0.w, hi.y, lo.y);
        pack2(r1.x, r1.y, hi.z, lo.z);
        pack2(r1.z, r1.w, hi.w, lo.w);
        size_t o = (size_t)m * KP + kq * 4;
        *(uint4*)&g_Wh[o] = hi;
        *(uint4*)&g_Wl[o] = lo;
    }
}

// ---------------------------------------------------------------------------
// Tensor-core GEMM: C[256,1024] = W @ X + bias per batch, bf16-split 3 passes
// (WhXh + WhXl + WlXh), fp32 accum. Block 256 thr = 8 warps (2m x 4n),
// BM=128, BN=128, warp tile 64x32, mma.sync m16n8k16.
// Fragments loaded by plain LDS.32 from bank-disjoint padded smem.
// ---------------------------------------------------------------------------
#define AS_STR 20     // 16 kp used + 4 pad  (banks: g*20+t all distinct mod 32)
#define XS_STR 136    // 128 n + 8 pad       (banks: t*136+g -> t*8+g distinct)

__device__ __forceinline__ void mma_bf16(float* d, const unsigned* a, unsigned b0, unsigned b1) {
    asm volatile(
        "mma.sync.aligned.m16n8k16.row.col.f32.bf16.bf16.f32 "
        "{%0,%1,%2,%3}, {%4,%5,%6,%7}, {%8,%9}, {%0,%1,%2,%3};"
        : "+f"(d[0]), "+f"(d[1]), "+f"(d[2]), "+f"(d[3])
        : "r"(a[0]), "r"(a[1]), "r"(a[2]), "r"(a[3]), "r"(b0), "r"(b1));
}

__global__ __launch_bounds__(256)
void gemm_mma_kernel(const float* __restrict__ bias) {
    const int n0 = blockIdx.x * 128;
    const int m0 = blockIdx.y * 128;
    const int bb = blockIdx.z;

    __shared__ unsigned As[128 * AS_STR];   // [m][kp] window of 16 kp
    __shared__ unsigned Xs[16 * XS_STR];    // [kp][n] window

    const int tid  = threadIdx.x;
    const int wid  = tid >> 5;
    const int lane = tid & 31;
    const int g    = lane >> 2;
    const int t    = lane & 3;
    const int warp_m = (wid >> 2) * 64;     // 0 / 64
    const int warp_n = (wid & 3) * 32;      // 0 / 32 / 64 / 96

    float acc[4][4][4];
    #pragma unroll
    for (int i = 0; i < 4; i++)
        #pragma unroll
        for (int j = 0; j < 4; j++)
            #pragma unroll
            for (int q = 0; q < 4; q++) acc[i][j][q] = 0.f;

    // staging indices
    const int arow = tid >> 1, ahalf = tid & 1;       // A: 128 rows x 2 halves
    const int xrow = tid >> 4, xc = (tid & 15) * 8;   // X: 16 rows x 16 chunks

    #pragma unroll
    for (int pass = 0; pass < 3; pass++) {
        const unsigned* Wsrc = (pass == 2) ? g_Wl : g_Wh;
        const unsigned* Xsrc = (pass == 1) ? g_Xl : g_Xh;
        const unsigned* wsp = Wsrc + (size_t)(m0 + arow) * KP + ahalf * 8;
        const unsigned* xsp = Xsrc + (size_t)(bb * KP + xrow) * VHW + n0 + xc;

        for (int kw = 0; kw < KP; kw += 16) {
            __syncthreads();
            {   // stage A 128x16kp
                uint4 v0 = *(const uint4*)(wsp + kw);
                uint4 v1 = *(const uint4*)(wsp + kw + 4);
                unsigned* d = &As[arow * AS_STR + ahalf * 8];
                *(uint4*)d = v0;
                *(uint4*)(d + 4) = v1;
            }
            {   // stage X 16x128
                uint4 v0 = *(const uint4*)(xsp + (size_t)kw * VHW);
                uint4 v1 = *(const uint4*)(xsp + (size_t)kw * VHW + 4);
                unsigned* d = &Xs[xrow * XS_STR + xc];
                *(uint4*)d = v0;
                *(uint4*)(d + 4) = v1;
            }
            __syncthreads();

            #pragma unroll
            for (int kb = 0; kb < 2; kb++) {
                unsigned af[4][4];
                #pragma unroll
                for (int mt = 0; mt < 4; mt++) {
                    const int ab = (warp_m + mt * 16 + g) * AS_STR + kb * 8 + t;
                    af[mt][0] = As[ab];
                    af[mt][1] = As[ab + 8 * AS_STR];
                    af[mt][2] = As[ab + 4];
                    af[mt][3] = As[ab + 8 * AS_STR + 4];
                }
                #pragma unroll
                for (int nt = 0; nt < 4; nt++) {
                    const int xb = (kb * 8 + t) * XS_STR + warp_n + nt * 8 + g;
                    unsigned b0 = Xs[xb];
                    unsigned b1 = Xs[xb + 4 * XS_STR];
                    #pragma unroll
                    for (int mt = 0; mt < 4; mt++)
                        mma_bf16(acc[mt][nt], af[mt], b0, b1);
                }
            }
        }
    }

    // epilogue: bias + store
    float* Cg = g_v + (size_t)bb * CH * VHW;
    #pragma unroll
    for (int mt = 0; mt < 4; mt++) {
        const int r0 = m0 + warp_m + mt * 16 + g;
        const float bv0 = bias[r0];
        const float bv1 = bias[r0 + 8];
        #pragma unroll
        for (int nt = 0; nt < 4; nt++) {
            const int c = n0 + warp_n + nt * 8 + 2 * t;
            float2 s0 = make_float2(acc[mt][nt][0] + bv0, acc[mt][nt][1] + bv0);
            float2 s1 = make_float2(acc[mt][nt][2] + bv1, acc[mt][nt][3] + bv1);
            *(float2*)&Cg[(size_t)r0 * VHW + c] = s0;
            *(float2*)&Cg[(size_t)(r0 + 8) * VHW + c] = s1;
        }
    }
}

// ---------------------------------------------------------------------------
// Phase 1: fused bilinear + partial sums over a 64-channel chunk.
// grid (4 chunks, 32 y-tiles, 8 b), 128 thr; tile 128(w) x 4(h), 4 px/thread.
// ---------------------------------------------------------------------------
#define CB_CCH   64
#define CB_ELEMS 102   // 3 rows * 34 cols

__global__ __launch_bounds__(128)
void cossim_part_kernel(const float* __restrict__ xcnn) {
    const int cc   = blockIdx.x;          // channel chunk
    const int by   = blockIdx.y;
    const int bb   = blockIdx.z;
    const int lane = threadIdx.x & 31;
    const int wrp  = threadIdx.x >> 5;
    const int y    = by * 4 + wrp;
    const int x0   = lane * 4;
    const int c0   = cc * CB_CCH;

    __shared__ float vsf[CB_CCH * CB_ELEMS];

    int gsrc[4];
    #pragma unroll
    for (int e = 0; e < 4; e++) {
        int idx = lane + 32 * e;
        int yy = idx / 34;
        int xx = idx - yy * 34;
        int gy = min(max(by - 1 + yy, 0), 31);
        int gx = min(max(xx - 1, 0), 31);
        gsrc[e] = gy * 32 + gx;
    }
    const bool valid3 = (lane + 96) < CB_ELEMS;

    const float fy = (wrp == 0) ? 0.625f : (wrp == 1) ? 0.875f
                   : (wrp == 2) ? 0.125f : 0.375f;
    const int rb = (wrp >= 2) ? 34 : 0;

    // stage coarse window for this chunk
    const float* vbase = g_v + (size_t)bb * CH * VHW;
    for (int c = wrp; c < CB_CCH; c += 4) {
        const float* vc = vbase + (size_t)(c0 + c) * VHW;
        float t0 = vc[gsrc[0]];
        float t1 = vc[gsrc[1]];
        float t2 = vc[gsrc[2]];
        float* d = &vsf[c * CB_ELEMS + lane];
        d[0] = t0; d[32] = t1; d[64] = t2;
        if (valid3) d[96] = vc[gsrc[3]];
    }
    __syncthreads();

    float dot0=0.f,dot1=0.f,dot2=0.f,dot3=0.f;
    float sc0=0.f,sc1=0.f,sc2=0.f,sc3=0.f;
    float sv0=0.f,sv1=0.f,sv2=0.f,sv3=0.f;

    const float* xc = xcnn + (size_t)(bb * CH + c0) * HWOUT + (size_t)y * W_OUT + x0;

    #pragma unroll 8
    for (int c = 0; c < CB_CCH; c++) {
        float4 x4 = *(const float4*)(xc + (size_t)c * HWOUT);
        const float* v0 = &vsf[c * CB_ELEMS + rb + lane];
        float a0 = v0[0],  a1 = v0[1],  a2 = v0[2];
        float b0 = v0[34], b1 = v0[35], b2 = v0[36];
        float cv0 = fmaf(fy, b0 - a0, a0);
        float cv1 = fmaf(fy, b1 - a1, a1);
        float cv2 = fmaf(fy, b2 - a2, a2);
        float d01 = cv1 - cv0, d12 = cv2 - cv1;
        float vu0 = fmaf(0.625f, d01, cv0);
        float vu1 = fmaf(0.875f, d01, cv0);
        float vu2 = fmaf(0.125f, d12, cv1);
        float vu3 = fmaf(0.375f, d12, cv1);
        dot0 = fmaf(x4.x, vu0, dot0); sc0 = fmaf(x4.x, x4.x, sc0); sv0 = fmaf(vu0, vu0, sv0);
        dot1 = fmaf(x4.y, vu1, dot1); sc1 = fmaf(x4.y, x4.y, sc1); sv1 = fmaf(vu1, vu1, sv1);
        dot2 = fmaf(x4.z, vu2, dot2); sc2 = fmaf(x4.z, x4.z, sc2); sv2 = fmaf(vu2, vu2, sv2);
        dot3 = fmaf(x4.w, vu3, dot3); sc3 = fmaf(x4.w, x4.w, sc3); sv3 = fmaf(vu3, vu3, sv3);
    }

    const size_t pix = (size_t)y * W_OUT + x0;
    float* p = g_part + ((size_t)((0 * 4 + cc) * BATCH + bb)) * HWOUT + pix;
    const size_t sstr = (size_t)4 * BATCH * HWOUT;
    *(float4*)(p)            = make_float4(dot0, dot1, dot2, dot3);
    *(float4*)(p + sstr)     = make_float4(sc0, sc1, sc2, sc3);
    *(float4*)(p + 2 * sstr) = make_float4(sv0, sv1, sv2, sv3);
}

// ---------------------------------------------------------------------------
// Phase 2: reduce 4 chunk-partials -> cosine similarity.
// ---------------------------------------------------------------------------
__global__ __launch_bounds__(256)
void cossim_reduce_kernel(float* __restrict__ out) {
    const int pix = blockIdx.x * 256 + threadIdx.x;   // 0..16383
    const int bb  = blockIdx.y;
    const size_t sstr = (size_t)4 * BATCH * HWOUT;
    const size_t cstr = (size_t)BATCH * HWOUT;
    const float* p = g_part + (size_t)bb * HWOUT + pix;

    float dot = 0.f, sc = 0.f, sv = 0.f;
    #pragma unroll
    for (int cc = 0; cc < 4; cc++) {
        dot += p[cc * cstr];
        sc  += p[cc * cstr + sstr];
        sv  += p[cc * cstr + 2 * sstr];
    }
    out[(size_t)bb * HWOUT + pix] = dot / (sqrtf(sc) * sqrtf(sv) + 1e-8f);
}

// ---------------------------------------------------------------------------
extern "C" void kernel_launch(void* const* d_in, const int* in_sizes, int n_in,
                              void* d_out, int out_size) {
    const float* x_cnn = (const float*)d_in[0];   // [8,256,128,128]
    const float* x_vit = (const float*)d_in[1];   // [8,512,32,32]
    const float* Wmat  = (const float*)d_in[2];   // [256,512]
    const float* bias  = (const float*)d_in[3];   // [256]
    float* out = (float*)d_out;                   // [8,1,128,128]

    convert_kernel<<<2048, 256>>>(x_vit, Wmat);
    gemm_mma_kernel<<<dim3(VHW / 128, CH / 128, BATCH), 256>>>(bias);
    cossim_part_kernel<<<dim3(4, H_OUT / 4, BATCH), 128>>>(x_cnn);
    cossim_reduce_kernel<<<dim3(HWOUT / 256, BATCH), 256>>>(out);
}

// round 4
// speedup vs baseline: 1.6071x; 1.1604x over previous
#include <cuda_runtime.h>
#include <cuda_bf16.h>
#include <cstdint>

#define BATCH 8
#define CH    256
#define KDIM  512
#define KP    256      // KDIM/2 packed bf16 pairs
#define VHW   1024     // 32*32
#define H_OUT 128
#define W_OUT 128
#define HWOUT (H_OUT * W_OUT)

// v scratch (8 MiB, L2-resident between kernels)
__device__ float g_v[BATCH * CH * VHW];
// cossim partials: [s(3)][chunk(8)][b(8)][pix(16384)] = 12.6 MB
#define NCHUNK 8
__device__ float g_part[3 * NCHUNK * BATCH * HWOUT];

// ---------------------------------------------------------------------------
// bf16 split helpers
// ---------------------------------------------------------------------------
__device__ __forceinline__ void pack2(float a, float b, unsigned& hi, unsigned& lo) {
    __nv_bfloat16 ha = __float2bfloat16(a);
    __nv_bfloat16 hb = __float2bfloat16(b);
    __nv_bfloat16 la = __float2bfloat16(a - __bfloat162float(ha));
    __nv_bfloat16 lb = __float2bfloat16(b - __bfloat162float(hb));
    hi = (unsigned)__bfloat16_as_ushort(ha) | ((unsigned)__bfloat16_as_ushort(hb) << 16);
    lo = (unsigned)__bfloat16_as_ushort(la) | ((unsigned)__bfloat16_as_ushort(lb) << 16);
}

__device__ __forceinline__ void mma_bf16(float* d, const unsigned* a, unsigned b0, unsigned b1) {
    asm volatile(
        "mma.sync.aligned.m16n8k16.row.col.f32.bf16.bf16.f32 "
        "{%0,%1,%2,%3}, {%4,%5,%6,%7}, {%8,%9}, {%0,%1,%2,%3};"
        : "+f"(d[0]), "+f"(d[1]), "+f"(d[2]), "+f"(d[3])
        : "r"(a[0]), "r"(a[1]), "r"(a[2]), "r"(a[3]), "r"(b0), "r"(b1));
}

// ---------------------------------------------------------------------------
// Fused convert + tensor-core GEMM: C[256,1024] = W @ X + bias per batch.
// bf16-split: C ≈ Wh*Xh + Wh*Xl + Wl*Xh, all accumulated in one k-loop from
// tiles staged ONCE per 32-k window. fp32 loaded with register prefetch,
// split to bf16 in regs, STS hi+lo. Block 256 thr = 8 warps (2m x 4n),
// BM=128, BN=128, warp tile 64x32.
// ---------------------------------------------------------------------------
#define AS_STR 20     // 16 kp + 4 pad: fragment banks g*20+t all distinct mod 32
#define XS_STR 136    // 128 n + 8 pad: fragment banks t*8+g distinct

__global__ __launch_bounds__(256)
void gemm_fused_kernel(const float* __restrict__ xvit,
                       const float* __restrict__ Wmat,
                       const float* __restrict__ bias) {
    const int n0 = blockIdx.x * 128;
    const int m0 = blockIdx.y * 128;
    const int bb = blockIdx.z;

    __shared__ unsigned Ash[128 * AS_STR];   // Wh [m][kp-window 16]
    __shared__ unsigned Asl[128 * AS_STR];   // Wl
    __shared__ unsigned Xsh[16 * XS_STR];    // Xh [kp][n]
    __shared__ unsigned Xsl[16 * XS_STR];    // Xl

    const int tid  = threadIdx.x;
    const int wid  = tid >> 5;
    const int lane = tid & 31;
    const int g    = lane >> 2;
    const int t4   = lane & 3;
    const int warp_m = (wid >> 2) * 64;
    const int warp_n = (wid & 3) * 32;

    // staging indices
    const int arow = tid >> 1, ahalf = tid & 1;       // A: 128 rows x 2 k-halves(16)
    const int xrow = tid >> 4, xc8 = (tid & 15) * 8;  // X: 16 kp-rows x 8-n chunks

    const float* wp = Wmat + (size_t)(m0 + arow) * KDIM + ahalf * 16;
    const float* xp = xvit + ((size_t)bb * KDIM + 2 * xrow) * VHW + n0 + xc8;

    float4 wa[4];   // 16 k of W (fp32)
    float4 xa[4];   // rows 2kp,2kp+1 x 8 n (fp32)

    // prefetch tile 0
    #pragma unroll
    for (int q = 0; q < 4; q++) wa[q] = *(const float4*)(wp + 4 * q);
    xa[0] = *(const float4*)(xp);
    xa[1] = *(const float4*)(xp + 4);
    xa[2] = *(const float4*)(xp + VHW);
    xa[3] = *(const float4*)(xp + VHW + 4);

    float acc[4][4][4];
    #pragma unroll
    for (int i = 0; i < 4; i++)
        #pragma unroll
        for (int j = 0; j < 4; j++)
            #pragma unroll
            for (int q = 0; q < 4; q++) acc[i][j][q] = 0.f;

    const int NT = KP / 16;   // 16 windows of 16 kp (32 k)
    for (int tw = 0; tw < NT; tw++) {
        // convert current regs -> bf16 hi/lo, STS
        {
            uint4 h0, l0, h1, l1;
            pack2(wa[0].x, wa[0].y, h0.x, l0.x);
            pack2(wa[0].z, wa[0].w, h0.y, l0.y);
            pack2(wa[1].x, wa[1].y, h0.z, l0.z);
            pack2(wa[1].z, wa[1].w, h0.w, l0.w);
            pack2(wa[2].x, wa[2].y, h1.x, l1.x);
            pack2(wa[2].z, wa[2].w, h1.y, l1.y);
            pack2(wa[3].x, wa[3].y, h1.z, l1.z);
            pack2(wa[3].z, wa[3].w, h1.w, l1.w);
            unsigned* dh = &Ash[arow * AS_STR + ahalf * 8];
            unsigned* dl = &Asl[arow * AS_STR + ahalf * 8];
            *(uint4*)dh = h0; *(uint4*)(dh + 4) = h1;
            *(uint4*)dl = l0; *(uint4*)(dl + 4) = l1;
        }
        {
            uint4 h0, l0, h1, l1;
            pack2(xa[0].x, xa[2].x, h0.x, l0.x);
            pack2(xa[0].y, xa[2].y, h0.y, l0.y);
            pack2(xa[0].z, xa[2].z, h0.z, l0.z);
            pack2(xa[0].w, xa[2].w, h0.w, l0.w);
            pack2(xa[1].x, xa[3].x, h1.x, l1.x);
            pack2(xa[1].y, xa[3].y, h1.y, l1.y);
            pack2(xa[1].z, xa[3].z, h1.z, l1.z);
            pack2(xa[1].w, xa[3].w, h1.w, l1.w);
            unsigned* dh = &Xsh[xrow * XS_STR + xc8];
            unsigned* dl = &Xsl[xrow * XS_STR + xc8];
            *(uint4*)dh = h0; *(uint4*)(dh + 4) = h1;
            *(uint4*)dl = l0; *(uint4*)(dl + 4) = l1;
        }
        __syncthreads();

        // prefetch next window (overlaps with MMA below)
        if (tw < NT - 1) {
            const float* wpn = wp + (tw + 1) * 32;
            const float* xpn = xp + (size_t)(tw + 1) * 32 * VHW;
            #pragma unroll
            for (int q = 0; q < 4; q++) wa[q] = *(const float4*)(wpn + 4 * q);
            xa[0] = *(const float4*)(xpn);
            xa[1] = *(const float4*)(xpn + 4);
            xa[2] = *(const float4*)(xpn + VHW);
            xa[3] = *(const float4*)(xpn + VHW + 4);
        }

        #pragma unroll
        for (int kb = 0; kb < 2; kb++) {
            unsigned ah[4][4], al[4][4];
            #pragma unroll
            for (int mt = 0; mt < 4; mt++) {
                const int ab = (warp_m + mt * 16 + g) * AS_STR + kb * 8 + t4;
                ah[mt][0] = Ash[ab];
                ah[mt][1] = Ash[ab + 8 * AS_STR];
                ah[mt][2] = Ash[ab + 4];
                ah[mt][3] = Ash[ab + 8 * AS_STR + 4];
                al[mt][0] = Asl[ab];
                al[mt][1] = Asl[ab + 8 * AS_STR];
                al[mt][2] = Asl[ab + 4];
                al[mt][3] = Asl[ab + 8 * AS_STR + 4];
            }
            #pragma unroll
            for (int nt = 0; nt < 4; nt++) {
                const int xb = (kb * 8 + t4) * XS_STR + warp_n + nt * 8 + g;
                unsigned bh0 = Xsh[xb];
                unsigned bh1 = Xsh[xb + 4 * XS_STR];
                unsigned bl0 = Xsl[xb];
                unsigned bl1 = Xsl[xb + 4 * XS_STR];
                #pragma unroll
                for (int mt = 0; mt < 4; mt++) {
                    mma_bf16(acc[mt][nt], ah[mt], bh0, bh1);  // hh
                    mma_bf16(acc[mt][nt], ah[mt], bl0, bl1);  // hl
                    mma_bf16(acc[mt][nt], al[mt], bh0, bh1);  // lh
                }
            }
        }
        __syncthreads();
    }

    // epilogue: bias + store
    float* Cg = g_v + (size_t)bb * CH * VHW;
    #pragma unroll
    for (int mt = 0; mt < 4; mt++) {
        const int r0 = m0 + warp_m + mt * 16 + g;
        const float bv0 = bias[r0];
        const float bv1 = bias[r0 + 8];
        #pragma unroll
        for (int nt = 0; nt < 4; nt++) {
            const int c = n0 + warp_n + nt * 8 + 2 * t4;
            *(float2*)&Cg[(size_t)r0 * VHW + c] =
                make_float2(acc[mt][nt][0] + bv0, acc[mt][nt][1] + bv0);
            *(float2*)&Cg[(size_t)(r0 + 8) * VHW + c] =
                make_float2(acc[mt][nt][2] + bv1, acc[mt][nt][3] + bv1);
        }
    }
}

// ---------------------------------------------------------------------------
// Phase 1: fused bilinear + partial cossim sums over a 32-channel chunk.
// grid (8 chunks, 32 y-tiles, 8 b) = 2048 blocks, 128 thr; 128(w)x4(h) tile,
// 4 px/thread via LDG.128.
// ---------------------------------------------------------------------------
#define CB_CCH   32
#define CB_ELEMS 102   // 3 rows * 34 cols

__global__ __launch_bounds__(128)
void cossim_part_kernel(const float* __restrict__ xcnn) {
    const int cc   = blockIdx.x;
    const int by   = blockIdx.y;
    const int bb   = blockIdx.z;
    const int lane = threadIdx.x & 31;
    const int wrp  = threadIdx.x >> 5;
    const int y    = by * 4 + wrp;
    const int x0   = lane * 4;
    const int c0   = cc * CB_CCH;

    __shared__ float vsf[CB_CCH * CB_ELEMS];

    int gsrc[4];
    #pragma unroll
    for (int e = 0; e < 4; e++) {
        int idx = lane + 32 * e;
        int yy = idx / 34;
        int xx = idx - yy * 34;
        int gy = min(max(by - 1 + yy, 0), 31);
        int gx = min(max(xx - 1, 0), 31);
        gsrc[e] = gy * 32 + gx;
    }
    const bool valid3 = (lane + 96) < CB_ELEMS;

    const float fy = (wrp == 0) ? 0.625f : (wrp == 1) ? 0.875f
                   : (wrp == 2) ? 0.125f : 0.375f;
    const int rb = (wrp >= 2) ? 34 : 0;

    const float* vbase = g_v + (size_t)bb * CH * VHW;
    for (int c = wrp; c < CB_CCH; c += 4) {
        const float* vc = vbase + (size_t)(c0 + c) * VHW;
        float t0 = vc[gsrc[0]];
        float t1 = vc[gsrc[1]];
        float t2 = vc[gsrc[2]];
        float* d = &vsf[c * CB_ELEMS + lane];
        d[0] = t0; d[32] = t1; d[64] = t2;
        if (valid3) d[96] = vc[gsrc[3]];
    }
    __syncthreads();

    float dot0=0.f,dot1=0.f,dot2=0.f,dot3=0.f;
    float sc0=0.f,sc1=0.f,sc2=0.f,sc3=0.f;
    float sv0=0.f,sv1=0.f,sv2=0.f,sv3=0.f;

    const float* xc = xcnn + (size_t)(bb * CH + c0) * HWOUT + (size_t)y * W_OUT + x0;

    #pragma unroll 8
    for (int c = 0; c < CB_CCH; c++) {
        float4 x4 = *(const float4*)(xc + (size_t)c * HWOUT);
        const float* v0 = &vsf[c * CB_ELEMS + rb + lane];
        float a0 = v0[0],  a1 = v0[1],  a2 = v0[2];
        float b0 = v0[34], b1 = v0[35], b2 = v0[36];
        float cv0 = fmaf(fy, b0 - a0, a0);
        float cv1 = fmaf(fy, b1 - a1, a1);
        float cv2 = fmaf(fy, b2 - a2, a2);
        float d01 = cv1 - cv0, d12 = cv2 - cv1;
        float vu0 = fmaf(0.625f, d01, cv0);
        float vu1 = fmaf(0.875f, d01, cv0);
        float vu2 = fmaf(0.125f, d12, cv1);
        float vu3 = fmaf(0.375f, d12, cv1);
        dot0 = fmaf(x4.x, vu0, dot0); sc0 = fmaf(x4.x, x4.x, sc0); sv0 = fmaf(vu0, vu0, sv0);
        dot1 = fmaf(x4.y, vu1, dot1); sc1 = fmaf(x4.y, x4.y, sc1); sv1 = fmaf(vu1, vu1, sv1);
        dot2 = fmaf(x4.z, vu2, dot2); sc2 = fmaf(x4.z, x4.z, sc2); sv2 = fmaf(vu2, vu2, sv2);
        dot3 = fmaf(x4.w, vu3, dot3); sc3 = fmaf(x4.w, x4.w, sc3); sv3 = fmaf(vu3, vu3, sv3);
    }

    const size_t pix = (size_t)y * W_OUT + x0;
    float* p = g_part + ((size_t)(cc * BATCH + bb)) * HWOUT + pix;
    const size_t sstr = (size_t)NCHUNK * BATCH * HWOUT;
    *(float4*)(p)            = make_float4(dot0, dot1, dot2, dot3);
    *(float4*)(p + sstr)     = make_float4(sc0, sc1, sc2, sc3);
    *(float4*)(p + 2 * sstr) = make_float4(sv0, sv1, sv2, sv3);
}

// ---------------------------------------------------------------------------
// Phase 2: reduce 8 chunk-partials -> cosine similarity. 4 px/thread (float4).
// ---------------------------------------------------------------------------
__global__ __launch_bounds__(256)
void cossim_reduce_kernel(float* __restrict__ out) {
    const int gid = blockIdx.x * 256 + threadIdx.x;   // 0..32767
    const size_t pix4 = (size_t)gid * 4;              // over b*HWOUT flattened
    const int bb  = (int)(pix4 >> 14);
    const size_t pix = pix4 & (HWOUT - 1);
    const size_t sstr = (size_t)NCHUNK * BATCH * HWOUT;
    const float* p = g_part + (size_t)bb * HWOUT + pix;
    const size_t cstr = (size_t)BATCH * HWOUT;

    float4 dot = make_float4(0.f, 0.f, 0.f, 0.f);
    float4 sc  = dot, sv = dot;
    #pragma unroll
    for (int cc = 0; cc < NCHUNK; cc++) {
        float4 d = *(const float4*)(p + cc * cstr);
        float4 a = *(const float4*)(p + cc * cstr + sstr);
        float4 b = *(const float4*)(p + cc * cstr + 2 * sstr);
        dot.x += d.x; dot.y += d.y; dot.z += d.z; dot.w += d.w;
        sc.x  += a.x; sc.y  += a.y; sc.z  += a.z; sc.w  += a.w;
        sv.x  += b.x; sv.y  += b.y; sv.z  += b.z; sv.w  += b.w;
    }
    float4 o;
    o.x = dot.x / (sqrtf(sc.x) * sqrtf(sv.x) + 1e-8f);
    o.y = dot.y / (sqrtf(sc.y) * sqrtf(sv.y) + 1e-8f);
    o.z = dot.z / (sqrtf(sc.z) * sqrtf(sv.z) + 1e-8f);
    o.w = dot.w / (sqrtf(sc.w) * sqrtf(sv.w) + 1e-8f);
    *(float4*)&out[pix4] = o;
}

// ---------------------------------------------------------------------------
extern "C" void kernel_launch(void* const* d_in, const int* in_sizes, int n_in,
                              void* d_out, int out_size) {
    const float* x_cnn = (const float*)d_in[0];   // [8,256,128,128]
    const float* x_vit = (const float*)d_in[1];   // [8,512,32,32]
    const float* Wmat  = (const float*)d_in[2];   // [256,512]
    const float* bias  = (const float*)d_in[3];   // [256]
    float* out = (float*)d_out;                   // [8,1,128,128]

    gemm_fused_kernel<<<dim3(VHW / 128, CH / 128, BATCH), 256>>>(x_vit, Wmat, bias);
    cossim_part_kernel<<<dim3(NCHUNK, H_OUT / 4, BATCH), 128>>>(x_cnn);
    cossim_reduce_kernel<<<dim3(BATCH * HWOUT / 4 / 256), 256>>>(out);
}

// round 5
// speedup vs baseline: 1.6262x; 1.0119x over previous
#include <cuda_runtime.h>
#include <cuda_bf16.h>
#include <cstdint>

#define BATCH 8
#define CH    256
#define KDIM  512
#define KP    256      // KDIM/2 packed bf16 pairs
#define VHW   1024     // 32*32
#define H_OUT 128
#define W_OUT 128
#define HWOUT (H_OUT * W_OUT)

// v scratch (8 MiB, L2-resident between kernels)
__device__ float g_v[BATCH * CH * VHW];
// cossim partials: [s(3)][chunk(8)][b(8)][pix(16384)] = 12.6 MB
#define NCHUNK 8
__device__ float g_part[3 * NCHUNK * BATCH * HWOUT];

// ---------------------------------------------------------------------------
// bf16 split helpers
// ---------------------------------------------------------------------------
__device__ __forceinline__ void pack2(float a, float b, unsigned& hi, unsigned& lo) {
    __nv_bfloat16 ha = __float2bfloat16(a);
    __nv_bfloat16 hb = __float2bfloat16(b);
    __nv_bfloat16 la = __float2bfloat16(a - __bfloat162float(ha));
    __nv_bfloat16 lb = __float2bfloat16(b - __bfloat162float(hb));
    hi = (unsigned)__bfloat16_as_ushort(ha) | ((unsigned)__bfloat16_as_ushort(hb) << 16);
    lo = (unsigned)__bfloat16_as_ushort(la) | ((unsigned)__bfloat16_as_ushort(lb) << 16);
}

__device__ __forceinline__ void mma_bf16(float* d, const unsigned* a, unsigned b0, unsigned b1) {
    asm volatile(
        "mma.sync.aligned.m16n8k16.row.col.f32.bf16.bf16.f32 "
        "{%0,%1,%2,%3}, {%4,%5,%6,%7}, {%8,%9}, {%0,%1,%2,%3};"
        : "+f"(d[0]), "+f"(d[1]), "+f"(d[2]), "+f"(d[3])
        : "r"(a[0]), "r"(a[1]), "r"(a[2]), "r"(a[3]), "r"(b0), "r"(b1));
}

// ---------------------------------------------------------------------------
// Fused convert + tensor-core GEMM, occupancy-tiled:
// BM=64, BN=64, 128 threads (4 warps, 32x32 warp tiles), grid (16,4,8)=512.
// bf16-split: C ≈ Wh*Xh + Wh*Xl + Wl*Xh in one k-loop from tiles staged once
// per 32-k window. fp32 reg-prefetch -> split in regs -> STS hi+lo.
// ---------------------------------------------------------------------------
#define AS_STR 20     // frag banks (g*20+t) all distinct mod 32
#define XS_STR 72     // frag banks (t*72+g) -> (8t+g) distinct mod 32

__global__ __launch_bounds__(128)
void gemm_fused_kernel(const float* __restrict__ xvit,
                       const float* __restrict__ Wmat,
                       const float* __restrict__ bias) {
    const int n0 = blockIdx.x * 64;
    const int m0 = blockIdx.y * 64;
    const int bb = blockIdx.z;

    __shared__ unsigned Ash[64 * AS_STR];   // Wh [m][16-kp window]
    __shared__ unsigned Asl[64 * AS_STR];   // Wl
    __shared__ unsigned Xsh[16 * XS_STR];   // Xh [kp][n]
    __shared__ unsigned Xsl[16 * XS_STR];   // Xl

    const int tid  = threadIdx.x;
    const int wid  = tid >> 5;
    const int lane = tid & 31;
    const int g    = lane >> 2;
    const int t4   = lane & 3;
    const int warp_m = (wid >> 1) * 32;
    const int warp_n = (wid & 1) * 32;

    // staging indices
    const int arow = tid >> 1, ahalf = tid & 1;       // A: 64 rows x 2 k-halves(16)
    const int xrow = tid >> 3, xc8 = (tid & 7) * 8;   // X: 16 kp-rows x 8-n chunks

    const float* wp = Wmat + (size_t)(m0 + arow) * KDIM + ahalf * 16;
    const float* xp = xvit + ((size_t)bb * KDIM + 2 * xrow) * VHW + n0 + xc8;

    float4 wa[4];   // 16 k of W
    float4 xa[4];   // rows 2kp,2kp+1 x 8 n

    #pragma unroll
    for (int q = 0; q < 4; q++) wa[q] = *(const float4*)(wp + 4 * q);
    xa[0] = *(const float4*)(xp);
    xa[1] = *(const float4*)(xp + 4);
    xa[2] = *(const float4*)(xp + VHW);
    xa[3] = *(const float4*)(xp + VHW + 4);

    float acc[2][4][4];
    #pragma unroll
    for (int i = 0; i < 2; i++)
        #pragma unroll
        for (int j = 0; j < 4; j++)
            #pragma unroll
            for (int q = 0; q < 4; q++) acc[i][j][q] = 0.f;

    const int NT = KP / 16;   // 16 windows of 32 k
    for (int tw = 0; tw < NT; tw++) {
        {   // A: split + STS (16 k = 8 kp per thread)
            uint4 h0, l0, h1, l1;
            pack2(wa[0].x, wa[0].y, h0.x, l0.x);
            pack2(wa[0].z, wa[0].w, h0.y, l0.y);
            pack2(wa[1].x, wa[1].y, h0.z, l0.z);
            pack2(wa[1].z, wa[1].w, h0.w, l0.w);
            pack2(wa[2].x, wa[2].y, h1.x, l1.x);
            pack2(wa[2].z, wa[2].w, h1.y, l1.y);
            pack2(wa[3].x, wa[3].y, h1.z, l1.z);
            pack2(wa[3].z, wa[3].w, h1.w, l1.w);
            unsigned* dh = &Ash[arow * AS_STR + ahalf * 8];
            unsigned* dl = &Asl[arow * AS_STR + ahalf * 8];
            *(uint4*)dh = h0; *(uint4*)(dh + 4) = h1;
            *(uint4*)dl = l0; *(uint4*)(dl + 4) = l1;
        }
        {   // X: split + STS (2 k-rows x 8 n per thread)
            uint4 h0, l0, h1, l1;
            pack2(xa[0].x, xa[2].x, h0.x, l0.x);
            pack2(xa[0].y, xa[2].y, h0.y, l0.y);
            pack2(xa[0].z, xa[2].z, h0.z, l0.z);
            pack2(xa[0].w, xa[2].w, h0.w, l0.w);
            pack2(xa[1].x, xa[3].x, h1.x, l1.x);
            pack2(xa[1].y, xa[3].y, h1.y, l1.y);
            pack2(xa[1].z, xa[3].z, h1.z, l1.z);
            pack2(xa[1].w, xa[3].w, h1.w, l1.w);
            unsigned* dh = &Xsh[xrow * XS_STR + xc8];
            unsigned* dl = &Xsl[xrow * XS_STR + xc8];
            *(uint4*)dh = h0; *(uint4*)(dh + 4) = h1;
            *(uint4*)dl = l0; *(uint4*)(dl + 4) = l1;
        }
        __syncthreads();

        if (tw < NT - 1) {   // prefetch next window (overlaps MMA)
            const float* wpn = wp + (tw + 1) * 32;
            const float* xpn = xp + (size_t)(tw + 1) * 32 * VHW;
            #pragma unroll
            for (int q = 0; q < 4; q++) wa[q] = *(const float4*)(wpn + 4 * q);
            xa[0] = *(const float4*)(xpn);
            xa[1] = *(const float4*)(xpn + 4);
            xa[2] = *(const float4*)(xpn + VHW);
            xa[3] = *(const float4*)(xpn + VHW + 4);
        }

        #pragma unroll
        for (int kb = 0; kb < 2; kb++) {
            unsigned ah[2][4], al[2][4];
            #pragma unroll
            for (int mt = 0; mt < 2; mt++) {
                const int ab = (warp_m + mt * 16 + g) * AS_STR + kb * 8 + t4;
                ah[mt][0] = Ash[ab];
                ah[mt][1] = Ash[ab + 8 * AS_STR];
                ah[mt][2] = Ash[ab + 4];
                ah[mt][3] = Ash[ab + 8 * AS_STR + 4];
                al[mt][0] = Asl[ab];
                al[mt][1] = Asl[ab + 8 * AS_STR];
                al[mt][2] = Asl[ab + 4];
                al[mt][3] = Asl[ab + 8 * AS_STR + 4];
            }
            #pragma unroll
            for (int nt = 0; nt < 4; nt++) {
                const int xb = (kb * 8 + t4) * XS_STR + warp_n + nt * 8 + g;
                unsigned bh0 = Xsh[xb];
                unsigned bh1 = Xsh[xb + 4 * XS_STR];
                unsigned bl0 = Xsl[xb];
                unsigned bl1 = Xsl[xb + 4 * XS_STR];
                #pragma unroll
                for (int mt = 0; mt < 2; mt++) {
                    mma_bf16(acc[mt][nt], ah[mt], bh0, bh1);  // hh
                    mma_bf16(acc[mt][nt], ah[mt], bl0, bl1);  // hl
                    mma_bf16(acc[mt][nt], al[mt], bh0, bh1);  // lh
                }
            }
        }
        __syncthreads();
    }

    // epilogue
    float* Cg = g_v + (size_t)bb * CH * VHW;
    #pragma unroll
    for (int mt = 0; mt < 2; mt++) {
        const int r0 = m0 + warp_m + mt * 16 + g;
        const float bv0 = bias[r0];
        const float bv1 = bias[r0 + 8];
        #pragma unroll
        for (int nt = 0; nt < 4; nt++) {
            const int c = n0 + warp_n + nt * 8 + 2 * t4;
            *(float2*)&Cg[(size_t)r0 * VHW + c] =
                make_float2(acc[mt][nt][0] + bv0, acc[mt][nt][1] + bv0);
            *(float2*)&Cg[(size_t)(r0 + 8) * VHW + c] =
                make_float2(acc[mt][nt][2] + bv1, acc[mt][nt][3] + bv1);
        }
    }
}

// ---------------------------------------------------------------------------
// Phase 1: fused bilinear + partial cossim sums over a 32-channel chunk.
// grid (8, 32, 8) = 2048 blocks, 128 thr; 128(w)x4(h) tile, 4 px/thread.
// ---------------------------------------------------------------------------
#define CB_CCH   32
#define CB_ELEMS 102   // 3 rows * 34 cols

__global__ __launch_bounds__(128)
void cossim_part_kernel(const float* __restrict__ xcnn) {
    const int cc   = blockIdx.x;
    const int by   = blockIdx.y;
    const int bb   = blockIdx.z;
    const int lane = threadIdx.x & 31;
    const int wrp  = threadIdx.x >> 5;
    const int y    = by * 4 + wrp;
    const int x0   = lane * 4;
    const int c0   = cc * CB_CCH;

    __shared__ float vsf[CB_CCH * CB_ELEMS];

    int gsrc[4];
    #pragma unroll
    for (int e = 0; e < 4; e++) {
        int idx = lane + 32 * e;
        int yy = idx / 34;
        int xx = idx - yy * 34;
        int gy = min(max(by - 1 + yy, 0), 31);
        int gx = min(max(xx - 1, 0), 31);
        gsrc[e] = gy * 32 + gx;
    }
    const bool valid3 = (lane + 96) < CB_ELEMS;

    const float fy = (wrp == 0) ? 0.625f : (wrp == 1) ? 0.875f
                   : (wrp == 2) ? 0.125f : 0.375f;
    const int rb = (wrp >= 2) ? 34 : 0;

    const float* vbase = g_v + (size_t)bb * CH * VHW;
    for (int c = wrp; c < CB_CCH; c += 4) {
        const float* vc = vbase + (size_t)(c0 + c) * VHW;
        float t0 = vc[gsrc[0]];
        float t1 = vc[gsrc[1]];
        float t2 = vc[gsrc[2]];
        float* d = &vsf[c * CB_ELEMS + lane];
        d[0] = t0; d[32] = t1; d[64] = t2;
        if (valid3) d[96] = vc[gsrc[3]];
    }
    __syncthreads();

    float dot0=0.f,dot1=0.f,dot2=0.f,dot3=0.f;
    float sc0=0.f,sc1=0.f,sc2=0.f,sc3=0.f;
    float sv0=0.f,sv1=0.f,sv2=0.f,sv3=0.f;

    const float* xc = xcnn + (size_t)(bb * CH + c0) * HWOUT + (size_t)y * W_OUT + x0;

    #pragma unroll 8
    for (int c = 0; c < CB_CCH; c++) {
        float4 x4 = *(const float4*)(xc + (size_t)c * HWOUT);
        const float* v0 = &vsf[c * CB_ELEMS + rb + lane];
        float a0 = v0[0],  a1 = v0[1],  a2 = v0[2];
        float b0 = v0[34], b1 = v0[35], b2 = v0[36];
        float cv0 = fmaf(fy, b0 - a0, a0);
        float cv1 = fmaf(fy, b1 - a1, a1);
        float cv2 = fmaf(fy, b2 - a2, a2);
        float d01 = cv1 - cv0, d12 = cv2 - cv1;
        float vu0 = fmaf(0.625f, d01, cv0);
        float vu1 = fmaf(0.875f, d01, cv0);
        float vu2 = fmaf(0.125f, d12, cv1);
        float vu3 = fmaf(0.375f, d12, cv1);
        dot0 = fmaf(x4.x, vu0, dot0); sc0 = fmaf(x4.x, x4.x, sc0); sv0 = fmaf(vu0, vu0, sv0);
        dot1 = fmaf(x4.y, vu1, dot1); sc1 = fmaf(x4.y, x4.y, sc1); sv1 = fmaf(vu1, vu1, sv1);
        dot2 = fmaf(x4.z, vu2, dot2); sc2 = fmaf(x4.z, x4.z, sc2); sv2 = fmaf(vu2, vu2, sv2);
        dot3 = fmaf(x4.w, vu3, dot3); sc3 = fmaf(x4.w, x4.w, sc3); sv3 = fmaf(vu3, vu3, sv3);
    }

    const size_t pix = (size_t)y * W_OUT + x0;
    float* p = g_part + ((size_t)(cc * BATCH + bb)) * HWOUT + pix;
    const size_t sstr = (size_t)NCHUNK * BATCH * HWOUT;
    *(float4*)(p)            = make_float4(dot0, dot1, dot2, dot3);
    *(float4*)(p + sstr)     = make_float4(sc0, sc1, sc2, sc3);
    *(float4*)(p + 2 * sstr) = make_float4(sv0, sv1, sv2, sv3);
}

// ---------------------------------------------------------------------------
// Phase 2: reduce 8 chunk-partials -> cosine similarity. 4 px/thread.
// ---------------------------------------------------------------------------
__global__ __launch_bounds__(256)
void cossim_reduce_kernel(float* __restrict__ out) {
    const int gid = blockIdx.x * 256 + threadIdx.x;   // 0..32767
    const size_t pix4 = (size_t)gid * 4;
    const int bb  = (int)(pix4 >> 14);
    const size_t pix = pix4 & (HWOUT - 1);
    const size_t sstr = (size_t)NCHUNK * BATCH * HWOUT;
    const float* p = g_part + (size_t)bb * HWOUT + pix;
    const size_t cstr = (size_t)BATCH * HWOUT;

    float4 dot = make_float4(0.f, 0.f, 0.f, 0.f);
    float4 sc  = dot, sv = dot;
    #pragma unroll
    for (int cc = 0; cc < NCHUNK; cc++) {
        float4 d = *(const float4*)(p + cc * cstr);
        float4 a = *(const float4*)(p + cc * cstr + sstr);
        float4 b = *(const float4*)(p + cc * cstr + 2 * sstr);
        dot.x += d.x; dot.y += d.y; dot.z += d.z; dot.w += d.w;
        sc.x  += a.x; sc.y  += a.y; sc.z  += a.z; sc.w  += a.w;
        sv.x  += b.x; sv.y  += b.y; sv.z  += b.z; sv.w  += b.w;
    }
    float4 o;
    o.x = dot.x / (sqrtf(sc.x) * sqrtf(sv.x) + 1e-8f);
    o.y = dot.y / (sqrtf(sc.y) * sqrtf(sv.y) + 1e-8f);
    o.z = dot.z / (sqrtf(sc.z) * sqrtf(sv.z) + 1e-8f);
    o.w = dot.w / (sqrtf(sc.w) * sqrtf(sv.w) + 1e-8f);
    *(float4*)&out[pix4] = o;
}

// ---------------------------------------------------------------------------
extern "C" void kernel_launch(void* const* d_in, const int* in_sizes, int n_in,
                              void* d_out, int out_size) {
    const float* x_cnn = (const float*)d_in[0];   // [8,256,128,128]
    const float* x_vit = (const float*)d_in[1];   // [8,512,32,32]
    const float* Wmat  = (const float*)d_in[2];   // [256,512]
    const float* bias  = (const float*)d_in[3];   // [256]
    float* out = (float*)d_out;                   // [8,1,128,128]

    gemm_fused_kernel<<<dim3(VHW / 64, CH / 64, BATCH), 128>>>(x_vit, Wmat, bias);
    cossim_part_kernel<<<dim3(NCHUNK, H_OUT / 4, BATCH), 128>>>(x_cnn);
    cossim_reduce_kernel<<<dim3(BATCH * HWOUT / 4 / 256), 256>>>(out);
}